// round 12
// baseline (speedup 1.0000x reference)
#include <cuda_runtime.h>
#include <cuda_bf16.h>
#include <math.h>

#define NB 65536
#define LH 64
#define GOALC 0.5f
#define MINPC (-1.2f)
#define UTHRESH 0.5f

typedef unsigned long long u64;

// ---- packed f32x2 primitives (single-slot FFMA2/FADD2/FMUL2 on sm_103a) ----
__device__ __forceinline__ u64 pk2(float lo, float hi) {
    u64 r; asm("mov.b64 %0, {%1, %2};" : "=l"(r) : "f"(lo), "f"(hi)); return r;
}
__device__ __forceinline__ void upk2(u64 v, float& lo, float& hi) {
    asm("mov.b64 {%0, %1}, %2;" : "=f"(lo), "=f"(hi) : "l"(v));
}
__device__ __forceinline__ u64 mul2(u64 a, u64 b) {
    u64 r; asm("mul.rn.f32x2 %0, %1, %2;" : "=l"(r) : "l"(a), "l"(b)); return r;
}
__device__ __forceinline__ u64 fma2(u64 a, u64 b, u64 c) {
    u64 r; asm("fma.rn.f32x2 %0, %1, %2, %3;" : "=l"(r) : "l"(a), "l"(b), "l"(c)); return r;
}
__device__ __forceinline__ u64 add2(u64 a, u64 b) {
    u64 r; asm("add.rn.f32x2 %0, %1, %2;" : "=l"(r) : "l"(a), "l"(b)); return r;
}

// XLA / Eigen rational tanh approximation for f32 (matches reference lowering).
__device__ __forceinline__ float xla_tanh(float xin) {
    const float x = fminf(fmaxf(xin, -7.99881172180175781f), 7.99881172180175781f);
    const float x2 = __fmul_rn(x, x);
    float p = __fmaf_rn(x2, -2.76076847742355e-16f, 2.00018790482477e-13f);
    p = __fmaf_rn(x2, p, -8.60467152213735e-11f);
    p = __fmaf_rn(x2, p, 5.12229709037114e-08f);
    p = __fmaf_rn(x2, p, 1.48572235717979e-05f);
    p = __fmaf_rn(x2, p, 6.37261928875436e-04f);
    p = __fmaf_rn(x2, p, 4.89352455891786e-03f);
    p = __fmul_rn(x, p);
    float q = __fmaf_rn(x2, 1.19825839466702e-06f, 1.18534705686654e-04f);
    q = __fmaf_rn(x2, q, 2.26843463243900e-03f);
    q = __fmaf_rn(x2, q, 4.89352518554385e-03f);
    const float r = __fdiv_rn(p, q);
    return (fabsf(xin) < 0.0004f) ? xin : r;
}

// fp32 cos (|x| <= ~3.8), Cody-Waite with residual carry, ~1-1.5 ulp.
__device__ __forceinline__ float cos_cw(float x) {
    const float kf = rintf(__fmul_rn(x, 0.63661977236758134f));
    const int k = (int)kf;
    const float DP1 = 1.5703125f;
    const float DP2 = 4.837512969970703125e-4f;
    const float DP3 = 7.549789948768648e-8f;
    const float t  = __fmaf_rn(-kf, DP1, x);
    const float rh = __fmaf_rn(-kf, DP2, t);
    float rl = __fsub_rn(__fsub_rn(t, rh), __fmul_rn(kf, DP2));
    rl = __fmaf_rn(-kf, DP3, rl);
    const float z = __fmul_rn(rh, rh);

    float pc = __fmaf_rn(z, 2.443315711809948e-5f, -1.388731625493765e-3f);
    pc = __fmaf_rn(z, pc, 4.166664568298827e-2f);
    float c = __fmaf_rn(z, -0.5f, 1.0f);
    c = __fmaf_rn(__fmul_rn(z, z), pc, c);
    c = __fmaf_rn(-rl, rh, c);

    float ps = __fmaf_rn(z, -1.9515295891e-4f, 8.3321608736e-3f);
    ps = __fmaf_rn(z, ps, -1.6666654611e-1f);
    float s = __fmaf_rn(__fmul_rn(rh, z), ps, rl);
    s = __fadd_rn(rh, s);

    const int q = k & 3;
    float r = (q & 1) ? s : c;
    if (q == 1 || q == 2) r = -r;
    return r;
}

// Largest float T in [0.4, 1.0] with xla_tanh(T) <= UTHRESH (bit bisection).
__device__ __forceinline__ float tanh_threshold() {
    unsigned a = __float_as_uint(0.4f);
    unsigned b = __float_as_uint(1.0f);
    while (b - a > 1u) {
        const unsigned m = a + (b - a) / 2u;
        if (xla_tanh(__uint_as_float(m)) <= UTHRESH) a = m; else b = m;
    }
    return __uint_as_float(a);
}

// Shared weight layout — packed by UNIT PAIRS (no duplication), as in R10/R11:
//   wxy[m] = { {W1[0][2m], W1[0][2m+1]}, {W1[1][2m], W1[1][2m+1]} }   m=0..31
//   wzh[q] = { {W2[4q]/2, W2[4q+1]/2}, {W2[4q+2]/2, W2[4q+3]/2} }     q=0..15
//   wbb[m] = { b1[2m], b1[2m+1] }
// Unit j accumulates into scalar lane (j mod 8) in increasing-j order,
// then the R6 scalar rn merge tree -> bit-identical to R6/R10/R11.
template<bool B1_ZERO>
__device__ __forceinline__ void run_agent(
    const ulonglong2* __restrict__ wxy,
    const ulonglong2* __restrict__ wzh,
    const u64* __restrict__ wbb,
    float bias2, float T, int n,
    float& p, float& v, float& u, float& a)
{
    const u64 ABSM = 0x7FFFFFFF7FFFFFFFULL;
    float lastPre = 0.0f;
    bool took = false;

    for (int t = 0; t < n; ++t) {
        if (p > GOALC) break;   // inactive is absorbing

        const bool rs = (p <= MINPC);
        const float pr = rs ? MINPC : p;
        const float vr = rs ? 0.0f : v;

        const u64 p2 = pk2(pr, pr);
        const u64 v2 = pk2(vr, vr);

        // 4 packed accumulators = 8 scalar lanes (R6 mapping)
        u64 S0 = 0, S1 = 0, S2 = 0, S3 = 0;
        #pragma unroll
        for (int q = 0; q < LH / 4; ++q) {         // 4 units per iteration
            const ulonglong2 xy0 = wxy[2 * q];      // units 4q, 4q+1
            const ulonglong2 xy1 = wxy[2 * q + 1];  // units 4q+2, 4q+3
            const ulonglong2 zz  = wzh[q];

            u64 d0 = fma2(v2, xy0.y, mul2(p2, xy0.x));
            u64 d1 = fma2(v2, xy1.y, mul2(p2, xy1.x));
            if (!B1_ZERO) {
                d0 = add2(d0, wbb[2 * q]);
                d1 = add2(d1, wbb[2 * q + 1]);
            }
            // relu(d)*wz + acc == fma(d+|d|, wz/2, acc), single rounding (exact)
            const u64 r0 = add2(d0, d0 & ABSM);
            const u64 r1 = add2(d1, d1 & ABSM);

            if ((q & 1) == 0) {   // units 4q..4q+3 -> lanes 0..3
                S0 = fma2(r0, zz.x, S0);
                S1 = fma2(r1, zz.y, S1);
            } else {              // lanes 4..7
                S2 = fma2(r0, zz.x, S2);
                S3 = fma2(r1, zz.y, S3);
            }
        }

        // unpack to the 8 scalar lanes, then R6's exact rn merge tree
        float l0, l1, l2, l3, l4, l5, l6, l7;
        upk2(S0, l0, l1); upk2(S1, l2, l3); upk2(S2, l4, l5); upk2(S3, l6, l7);
        const float dot =
            __fadd_rn(__fadd_rn(__fadd_rn(l0, l1), __fadd_rn(l2, l3)),
                      __fadd_rn(__fadd_rn(l4, l5), __fadd_rn(l6, l7)));
        const float pre = __fadd_rn(dot, bias2);

        // un via hoisted tanh threshold (validated bit-exact R9-R11)
        const float un = (pre <= T) ? -1.0f : 1.0f;

        const float c  = cos_cw(__fmul_rn(3.0f, pr));
        const float vn = __fsub_rn(__fadd_rn(vr, __fmul_rn(un, 0.0015f)),
                                   __fmul_rn(0.0025f, c));
        const float pn = __fadd_rn(pr, vn);

        p = pn; v = vn; u = un; lastPre = pre; took = true;
    }

    if (took) a = xla_tanh(lastPre);
}

__global__ __launch_bounds__(64)   // uncapped regs; 2048 warps resident
void mc_kernel(const float4* __restrict__ x,
               const float* __restrict__ W1,
               const float* __restrict__ b1,
               const float* __restrict__ W2,
               const float* __restrict__ b2,
               const int* __restrict__ n_steps,
               float4* __restrict__ out)
{
    __shared__ ulonglong2 wxy[LH / 2];
    __shared__ ulonglong2 wzh[LH / 4];
    __shared__ u64 wbb[LH / 2];

    const int tid = threadIdx.x;   // 0..63
    int zok = 1;
    if (tid < LH / 2) {
        const int j0 = 2 * tid, j1 = 2 * tid + 1;
        wxy[tid] = make_ulonglong2(pk2(W1[j0], W1[j1]),
                                   pk2(W1[LH + j0], W1[LH + j1]));
        const float bv0 = b1[j0], bv1 = b1[j1];
        wbb[tid] = pk2(bv0, bv1);
        zok = (__float_as_uint(bv0) == 0u) && (__float_as_uint(bv1) == 0u);
    }
    if (tid < LH / 4) {
        const int j = 4 * tid;
        wzh[tid] = make_ulonglong2(
            pk2(__fmul_rn(0.5f, W2[j]),     __fmul_rn(0.5f, W2[j + 1])),
            pk2(__fmul_rn(0.5f, W2[j + 2]), __fmul_rn(0.5f, W2[j + 3])));
    }
    const int b1_zero = __syncthreads_and(zok);

    const float bias2 = b2[0];
    const float T = tanh_threshold();
    const int n = n_steps ? n_steps[0] : 64;

    const int i = blockIdx.x * blockDim.x + tid;   // 1 agent per thread

    const float4 s = x[i];
    float p = s.x, v = s.y, u = s.z, a = s.w;

    if (b1_zero) run_agent<true >(wxy, wzh, wbb, bias2, T, n, p, v, u, a);
    else         run_agent<false>(wxy, wzh, wbb, bias2, T, n, p, v, u, a);

    out[i] = make_float4(p, v, u, a);
}

extern "C" void kernel_launch(void* const* d_in, const int* in_sizes, int n_in,
                              void* d_out, int out_size) {
    const float* x  = (const float*)d_in[0];
    const float* W1 = (const float*)d_in[1];
    const float* b1 = (const float*)d_in[2];
    const float* W2 = (const float*)d_in[3];
    const float* b2 = (const float*)d_in[4];
    const int* ns   = (n_in >= 6) ? (const int*)d_in[5] : nullptr;

    mc_kernel<<<NB / 64, 64>>>((const float4*)x, W1, b1, W2, b2, ns,
                               (float4*)d_out);
}